// round 1
// baseline (speedup 1.0000x reference)
#include <cuda_runtime.h>
#include <math.h>
#include <stdint.h>

#define BATCH 8192
#define KDIM  1024   // I == H == 1024
#define HDIM  1024
#define FH    4096   // 4*H

// Scratch for raw (pre-LayerNorm) gate pre-activations.
__device__ float g_ig[(size_t)BATCH * FH];   // input @ W_ih^T
__device__ float g_hg[(size_t)BATCH * FH];   // hx    @ W_hh^T

// ---------------------------------------------------------------------------
// GEMM: out[m,n] = sum_k A[m,k] * W[n,k]   (A: [B,K] row-major, W: [FH,K] row-major)
// TF32 mma.sync m16n8k8, 128x128x32 CTA tile, 8 warps (2x4), 64x32 warp tile.
// ---------------------------------------------------------------------------
#define BM 128
#define BN 128
#define BK 32
#define SPAD 4

__device__ __forceinline__ float to_tf32(float x) {
    uint32_t u;
    asm("cvt.rna.tf32.f32 %0, %1;" : "=r"(u) : "f"(x));
    return __uint_as_float(u);
}

__device__ __forceinline__ void mma_tf32(float c[4], const uint32_t a[4], const uint32_t b[2]) {
    asm volatile(
        "mma.sync.aligned.m16n8k8.row.col.f32.tf32.tf32.f32 "
        "{%0,%1,%2,%3}, {%4,%5,%6,%7}, {%8,%9}, {%0,%1,%2,%3};"
        : "+f"(c[0]), "+f"(c[1]), "+f"(c[2]), "+f"(c[3])
        : "r"(a[0]), "r"(a[1]), "r"(a[2]), "r"(a[3]),
          "r"(b[0]), "r"(b[1]));
}

__global__ void __launch_bounds__(256)
gemm_tf32_kernel(const float* __restrict__ input, const float* __restrict__ hx,
                 const float* __restrict__ wih,   const float* __restrict__ whh)
{
    const float* A   = (blockIdx.z == 0) ? input : hx;
    const float* W   = (blockIdx.z == 0) ? wih   : whh;
    float*       out = (blockIdx.z == 0) ? g_ig  : g_hg;

    __shared__ float As[BM][BK + SPAD];
    __shared__ float Ws[BN][BK + SPAD];

    const int tid  = threadIdx.x;
    const int warp = tid >> 5;
    const int lane = tid & 31;
    const int wm   = warp >> 2;   // 0..1  -> 64-row slab
    const int wn   = warp & 3;    // 0..3  -> 32-col slab
    const int m0   = blockIdx.y * BM;
    const int n0   = blockIdx.x * BN;

    // global->smem loader mapping: each thread loads 4 float4 per tile
    const int ldrow = tid >> 3;        // 0..31
    const int ldcol = (tid & 7) * 4;   // 0,4,...,28

    float acc[4][4][4];
    #pragma unroll
    for (int mt = 0; mt < 4; mt++)
        #pragma unroll
        for (int nt = 0; nt < 4; nt++)
            #pragma unroll
            for (int r = 0; r < 4; r++)
                acc[mt][nt][r] = 0.f;

    for (int kt = 0; kt < KDIM; kt += BK) {
        #pragma unroll
        for (int p = 0; p < 4; p++) {
            int row = ldrow + p * 32;
            float4 va = *(const float4*)&A[(size_t)(m0 + row) * KDIM + kt + ldcol];
            As[row][ldcol + 0] = to_tf32(va.x);
            As[row][ldcol + 1] = to_tf32(va.y);
            As[row][ldcol + 2] = to_tf32(va.z);
            As[row][ldcol + 3] = to_tf32(va.w);
            float4 vw = *(const float4*)&W[(size_t)(n0 + row) * KDIM + kt + ldcol];
            Ws[row][ldcol + 0] = to_tf32(vw.x);
            Ws[row][ldcol + 1] = to_tf32(vw.y);
            Ws[row][ldcol + 2] = to_tf32(vw.z);
            Ws[row][ldcol + 3] = to_tf32(vw.w);
        }
        __syncthreads();

        #pragma unroll
        for (int kk = 0; kk < BK; kk += 8) {
            uint32_t af[4][4];
            #pragma unroll
            for (int mt = 0; mt < 4; mt++) {
                int r = wm * 64 + mt * 16 + (lane >> 2);
                int c = kk + (lane & 3);
                af[mt][0] = __float_as_uint(As[r][c]);
                af[mt][1] = __float_as_uint(As[r + 8][c]);
                af[mt][2] = __float_as_uint(As[r][c + 4]);
                af[mt][3] = __float_as_uint(As[r + 8][c + 4]);
            }
            uint32_t bf[4][2];
            #pragma unroll
            for (int nt = 0; nt < 4; nt++) {
                int n = wn * 32 + nt * 8 + (lane >> 2);
                int c = kk + (lane & 3);
                bf[nt][0] = __float_as_uint(Ws[n][c]);
                bf[nt][1] = __float_as_uint(Ws[n][c + 4]);
            }
            #pragma unroll
            for (int mt = 0; mt < 4; mt++)
                #pragma unroll
                for (int nt = 0; nt < 4; nt++)
                    mma_tf32(acc[mt][nt], af[mt], bf[nt]);
        }
        __syncthreads();
    }

    // store accumulators
    #pragma unroll
    for (int mt = 0; mt < 4; mt++) {
        int row0 = m0 + wm * 64 + mt * 16 + (lane >> 2);
        #pragma unroll
        for (int nt = 0; nt < 4; nt++) {
            int col0 = n0 + wn * 32 + nt * 8 + 2 * (lane & 3);
            float2 v0 = make_float2(acc[mt][nt][0], acc[mt][nt][1]);
            float2 v1 = make_float2(acc[mt][nt][2], acc[mt][nt][3]);
            *(float2*)&out[(size_t)row0 * FH + col0]       = v0;
            *(float2*)&out[(size_t)(row0 + 8) * FH + col0] = v1;
        }
    }
}

// ---------------------------------------------------------------------------
// Fused LayerNorm + LSTM gates + cell LayerNorm. One CTA (256 threads) per row.
// ---------------------------------------------------------------------------
__device__ __forceinline__ float sigmoidf_(float x) {
    return 1.f / (1.f + expf(-x));
}

// block reduce sum over 256 threads; sh must have >=8 floats, unique per call site region
__device__ __forceinline__ float block_sum(float v, float* sh) {
    #pragma unroll
    for (int o = 16; o > 0; o >>= 1) v += __shfl_down_sync(0xffffffffu, v, o);
    int lane = threadIdx.x & 31, w = threadIdx.x >> 5;
    if (lane == 0) sh[w] = v;
    __syncthreads();
    if (w == 0) {
        float t = (lane < 8) ? sh[lane] : 0.f;
        #pragma unroll
        for (int o = 4; o > 0; o >>= 1) t += __shfl_down_sync(0xffffffffu, t, o);
        if (lane == 0) sh[0] = t;
    }
    __syncthreads();
    return sh[0];
}

__global__ void __launch_bounds__(256)
fuse_kernel(const float* __restrict__ cx,
            const float* __restrict__ ln_i_w, const float* __restrict__ ln_i_b,
            const float* __restrict__ ln_h_w, const float* __restrict__ ln_h_b,
            const float* __restrict__ ln_c_w, const float* __restrict__ ln_c_b,
            float* __restrict__ out)
{
    const int b   = blockIdx.x;
    const int tid = threadIdx.x;
    const float* ig = g_ig + (size_t)b * FH;
    const float* hg = g_hg + (size_t)b * FH;

    __shared__ float gates[FH];
    __shared__ float red0[8], red1[8], red2[8], red3[8], red4[8], red5[8];

    float vi[16], vh[16];
    float s_i = 0.f, ss_i = 0.f, s_h = 0.f, ss_h = 0.f;
    #pragma unroll
    for (int p = 0; p < 16; p++) {
        int j = tid + p * 256;
        float a = ig[j];
        float c = hg[j];
        vi[p] = a; vh[p] = c;
        s_i += a; ss_i += a * a;
        s_h += c; ss_h += c * c;
    }
    float sum_i  = block_sum(s_i,  red0);
    float sumq_i = block_sum(ss_i, red1);
    float sum_h  = block_sum(s_h,  red2);
    float sumq_h = block_sum(ss_h, red3);

    const float inv_fh = 1.f / (float)FH;
    float mu_i  = sum_i * inv_fh;
    float var_i = sumq_i * inv_fh - mu_i * mu_i;
    float rs_i  = rsqrtf(var_i + 1e-5f);
    float mu_h  = sum_h * inv_fh;
    float var_h = sumq_h * inv_fh - mu_h * mu_h;
    float rs_h  = rsqrtf(var_h + 1e-5f);

    #pragma unroll
    for (int p = 0; p < 16; p++) {
        int j = tid + p * 256;
        float gi = (vi[p] - mu_i) * rs_i * ln_i_w[j] + ln_i_b[j];
        float gh = (vh[p] - mu_h) * rs_h * ln_h_w[j] + ln_h_b[j];
        gates[j] = gi + gh;
    }
    __syncthreads();

    // cell state: c = sigmoid(f)*cx + sigmoid(i)*tanh(g)
    float cvals[4];
    float s_c = 0.f, ss_c = 0.f;
    #pragma unroll
    for (int p = 0; p < 4; p++) {
        int h  = tid + p * 256;
        float in_g = sigmoidf_(gates[h]);
        float f_g  = sigmoidf_(gates[HDIM + h]);
        float g_g  = tanhf(gates[2 * HDIM + h]);
        float c = f_g * cx[(size_t)b * HDIM + h] + in_g * g_g;
        cvals[p] = c;
        s_c += c; ss_c += c * c;
    }
    float sum_c  = block_sum(s_c,  red4);
    float sumq_c = block_sum(ss_c, red5);
    const float inv_h = 1.f / (float)HDIM;
    float mu_c  = sum_c * inv_h;
    float var_c = sumq_c * inv_h - mu_c * mu_c;
    float rs_c  = rsqrtf(var_c + 1e-5f);

    #pragma unroll
    for (int p = 0; p < 4; p++) {
        int h = tid + p * 256;
        float cy = (cvals[p] - mu_c) * rs_c * ln_c_w[h] + ln_c_b[h];
        float o_g = sigmoidf_(gates[3 * HDIM + h]);
        float hy = o_g * tanhf(cy);
        out[(size_t)b * HDIM + h] = hy;                           // hy block
        out[(size_t)BATCH * HDIM + (size_t)b * HDIM + h] = cy;    // cy block
    }
}

// ---------------------------------------------------------------------------
extern "C" void kernel_launch(void* const* d_in, const int* in_sizes, int n_in,
                              void* d_out, int out_size)
{
    const float* input  = (const float*)d_in[0];
    const float* hx     = (const float*)d_in[1];
    const float* cx     = (const float*)d_in[2];
    const float* wih    = (const float*)d_in[3];
    const float* whh    = (const float*)d_in[4];
    const float* ln_i_w = (const float*)d_in[5];
    const float* ln_i_b = (const float*)d_in[6];
    const float* ln_h_w = (const float*)d_in[7];
    const float* ln_h_b = (const float*)d_in[8];
    const float* ln_c_w = (const float*)d_in[9];
    const float* ln_c_b = (const float*)d_in[10];
    float* out = (float*)d_out;

    dim3 grid(FH / BN, BATCH / BM, 2);
    gemm_tf32_kernel<<<grid, 256>>>(input, hx, wih, whh);
    fuse_kernel<<<BATCH, 256>>>(cx, ln_i_w, ln_i_b, ln_h_w, ln_h_b, ln_c_w, ln_c_b, out);
}

// round 3
// speedup vs baseline: 1.4262x; 1.4262x over previous
#include <cuda_runtime.h>
#include <math.h>
#include <stdint.h>

#define BATCH 8192
#define KDIM  1024
#define HDIM  1024
#define FH    4096

// Scratch: raw gate pre-activations + tf32-prerounded operand copies.
__device__ float g_ig[(size_t)BATCH * FH];
__device__ float g_hg[(size_t)BATCH * FH];
__device__ float g_A [(size_t)BATCH * KDIM];   // input, tf32-rounded
__device__ float g_H [(size_t)BATCH * KDIM];   // hx, tf32-rounded
__device__ float g_Wi[(size_t)FH * KDIM];      // weight_ih, tf32-rounded
__device__ float g_Wh[(size_t)FH * KDIM];      // weight_hh, tf32-rounded

// ---------------------------------------------------------------------------
// tf32 pre-rounding kernel (RNA). Grid-stride over float4.
// ---------------------------------------------------------------------------
__device__ __forceinline__ float to_tf32(float x) {
    uint32_t u;
    asm("cvt.rna.tf32.f32 %0, %1;" : "=r"(u) : "f"(x));
    return __uint_as_float(u);
}

__global__ void __launch_bounds__(256)
round_tf32_kernel(const float* __restrict__ src, float* __restrict__ dst, int n4)
{
    int i = blockIdx.x * blockDim.x + threadIdx.x;
    int stride = gridDim.x * blockDim.x;
    for (; i < n4; i += stride) {
        float4 v = ((const float4*)src)[i];
        v.x = to_tf32(v.x); v.y = to_tf32(v.y);
        v.z = to_tf32(v.z); v.w = to_tf32(v.w);
        ((float4*)dst)[i] = v;
    }
}

// ---------------------------------------------------------------------------
// GEMM: out[m,n] = sum_k A[m,k] * W[n,k]  via mma.sync tf32, cp.async pipeline
// CTA tile 128x256x32, 3 stages, 8 warps (2x4), warp tile 64x64.
// ---------------------------------------------------------------------------
#define BM 128
#define BN 256
#define BK 32
#define STAGES 3
#define NCHUNK (KDIM / BK)          // 32
#define ROWW  (BK + 4)              // 36 floats per smem row (padded)
#define A_BYTES (BM * ROWW * 4)     // 18432
#define B_BYTES (BN * ROWW * 4)     // 36864
#define STAGE_BYTES (A_BYTES + B_BYTES)   // 55296
#define SMEM_TOTAL (STAGES * STAGE_BYTES) // 165888

__device__ __forceinline__ uint32_t smem_u32(const void* p) {
    uint32_t a;
    asm("{ .reg .u64 t; cvta.to.shared.u64 t, %1; cvt.u32.u64 %0, t; }" : "=r"(a) : "l"(p));
    return a;
}

__device__ __forceinline__ void cp16(uint32_t saddr, const void* g) {
    asm volatile("cp.async.cg.shared.global [%0], [%1], 16;" :: "r"(saddr), "l"(g));
}
#define CP_COMMIT() asm volatile("cp.async.commit_group;" ::: "memory")
#define CP_WAIT_1() asm volatile("cp.async.wait_group 1;" ::: "memory")
#define CP_WAIT_0() asm volatile("cp.async.wait_group 0;" ::: "memory")

__device__ __forceinline__ void mma_tf32(float c[4], const uint32_t a[4], const uint32_t b[2]) {
    asm volatile(
        "mma.sync.aligned.m16n8k8.row.col.f32.tf32.tf32.f32 "
        "{%0,%1,%2,%3}, {%4,%5,%6,%7}, {%8,%9}, {%0,%1,%2,%3};"
        : "+f"(c[0]), "+f"(c[1]), "+f"(c[2]), "+f"(c[3])
        : "r"(a[0]), "r"(a[1]), "r"(a[2]), "r"(a[3]),
          "r"(b[0]), "r"(b[1]));
}

__global__ void __launch_bounds__(256, 1)
gemm_tc_kernel(const float* __restrict__ gA, const float* __restrict__ gH,
               const float* __restrict__ gWi, const float* __restrict__ gWh)
{
    extern __shared__ char smem[];
    const uint32_t sbase = smem_u32(smem);

    const float* A   = (blockIdx.z == 0) ? gA  : gH;
    const float* W   = (blockIdx.z == 0) ? gWi : gWh;
    float*       out = (blockIdx.z == 0) ? g_ig : g_hg;

    const int tid  = threadIdx.x;
    const int wid  = tid >> 5;
    const int lane = tid & 31;
    const int wm   = wid >> 2;     // 0..1 -> 64-row slab
    const int wn   = wid & 3;      // 0..3 -> 64-col slab
    const int m0   = blockIdx.y * BM;
    const int n0   = blockIdx.x * BN;

    // loader mapping: idx -> (row, 16B-chunk)
    // A: 1024 chunks (128 rows x 8); B: 2048 chunks (256 rows x 8)
    const int ldrowA[4] = { (tid + 0*256) >> 3, (tid + 1*256) >> 3,
                            (tid + 2*256) >> 3, (tid + 3*256) >> 3 };
    const int ldc4 = (tid & 7);    // 0..7 (chunk of 4 floats)

    // issue cp.asyncs for one stage/chunk
    auto load_stage = [&](int st, int c) {
        const uint32_t sA = sbase + st * STAGE_BYTES;
        const uint32_t sB = sA + A_BYTES;
        const int kt = c * BK;
        #pragma unroll
        for (int i = 0; i < 4; i++) {
            int row = ldrowA[i];
            cp16(sA + (row * ROWW + ldc4 * 4) * 4,
                 &A[(size_t)(m0 + row) * KDIM + kt + ldc4 * 4]);
        }
        #pragma unroll
        for (int i = 0; i < 8; i++) {
            int row = (tid + i * 256) >> 3;
            cp16(sB + (row * ROWW + ldc4 * 4) * 4,
                 &W[(size_t)(n0 + row) * KDIM + kt + ldc4 * 4]);
        }
    };

    float acc[4][8][4];
    #pragma unroll
    for (int mt = 0; mt < 4; mt++)
        #pragma unroll
        for (int nt = 0; nt < 8; nt++)
            #pragma unroll
            for (int r = 0; r < 4; r++)
                acc[mt][nt][r] = 0.f;

    // prologue: fill STAGES-1 stages
    load_stage(0, 0); CP_COMMIT();
    load_stage(1, 1); CP_COMMIT();

    for (int c = 0; c < NCHUNK; c++) {
        CP_WAIT_1();           // stage for chunk c is complete
        __syncthreads();       // all warps done with buffer about to be overwritten

        if (c + 2 < NCHUNK) load_stage((c + 2) % STAGES, c + 2);
        CP_COMMIT();

        const uint32_t sA = sbase + (c % STAGES) * STAGE_BYTES;
        const uint32_t sB = sA + A_BYTES;
        const float* As = (const float*)(smem + (c % STAGES) * STAGE_BYTES);
        const float* Bs = As + BM * ROWW;
        (void)sA; (void)sB;

        #pragma unroll
        for (int kk = 0; kk < BK; kk += 8) {
            uint32_t af[4][4];
            #pragma unroll
            for (int mt = 0; mt < 4; mt++) {
                int r = wm * 64 + mt * 16 + (lane >> 2);
                int col = kk + (lane & 3);
                af[mt][0] = __float_as_uint(As[r * ROWW + col]);
                af[mt][1] = __float_as_uint(As[(r + 8) * ROWW + col]);
                af[mt][2] = __float_as_uint(As[r * ROWW + col + 4]);
                af[mt][3] = __float_as_uint(As[(r + 8) * ROWW + col + 4]);
            }
            uint32_t bf[8][2];
            #pragma unroll
            for (int nt = 0; nt < 8; nt++) {
                int n = wn * 64 + nt * 8 + (lane >> 2);
                int col = kk + (lane & 3);
                bf[nt][0] = __float_as_uint(Bs[n * ROWW + col]);
                bf[nt][1] = __float_as_uint(Bs[n * ROWW + col + 4]);
            }
            #pragma unroll
            for (int mt = 0; mt < 4; mt++)
                #pragma unroll
                for (int nt = 0; nt < 8; nt++)
                    mma_tf32(acc[mt][nt], af[mt], bf[nt]);
        }
    }

    // epilogue: store accumulators
    #pragma unroll
    for (int mt = 0; mt < 4; mt++) {
        int row0 = m0 + wm * 64 + mt * 16 + (lane >> 2);
        #pragma unroll
        for (int nt = 0; nt < 8; nt++) {
            int col0 = n0 + wn * 64 + nt * 8 + 2 * (lane & 3);
            *(float2*)&out[(size_t)row0 * FH + col0] =
                make_float2(acc[mt][nt][0], acc[mt][nt][1]);
            *(float2*)&out[(size_t)(row0 + 8) * FH + col0] =
                make_float2(acc[mt][nt][2], acc[mt][nt][3]);
        }
    }
}

// ---------------------------------------------------------------------------
// Fused LayerNorm + LSTM gates + cell LayerNorm (unchanged).
// ---------------------------------------------------------------------------
__device__ __forceinline__ float sigmoidf_(float x) {
    return 1.f / (1.f + expf(-x));
}

__device__ __forceinline__ float block_sum(float v, float* sh) {
    #pragma unroll
    for (int o = 16; o > 0; o >>= 1) v += __shfl_down_sync(0xffffffffu, v, o);
    int lane = threadIdx.x & 31, w = threadIdx.x >> 5;
    if (lane == 0) sh[w] = v;
    __syncthreads();
    if (w == 0) {
        float t = (lane < 8) ? sh[lane] : 0.f;
        #pragma unroll
        for (int o = 4; o > 0; o >>= 1) t += __shfl_down_sync(0xffffffffu, t, o);
        if (lane == 0) sh[0] = t;
    }
    __syncthreads();
    return sh[0];
}

__global__ void __launch_bounds__(256)
fuse_kernel(const float* __restrict__ cx,
            const float* __restrict__ ln_i_w, const float* __restrict__ ln_i_b,
            const float* __restrict__ ln_h_w, const float* __restrict__ ln_h_b,
            const float* __restrict__ ln_c_w, const float* __restrict__ ln_c_b,
            float* __restrict__ out)
{
    const int b   = blockIdx.x;
    const int tid = threadIdx.x;
    const float* ig = g_ig + (size_t)b * FH;
    const float* hg = g_hg + (size_t)b * FH;

    __shared__ float gates[FH];
    __shared__ float red0[8], red1[8], red2[8], red3[8], red4[8], red5[8];

    float vi[16], vh[16];
    float s_i = 0.f, ss_i = 0.f, s_h = 0.f, ss_h = 0.f;
    #pragma unroll
    for (int p = 0; p < 16; p++) {
        int j = tid + p * 256;
        float a = ig[j];
        float c = hg[j];
        vi[p] = a; vh[p] = c;
        s_i += a; ss_i += a * a;
        s_h += c; ss_h += c * c;
    }
    float sum_i  = block_sum(s_i,  red0);
    float sumq_i = block_sum(ss_i, red1);
    float sum_h  = block_sum(s_h,  red2);
    float sumq_h = block_sum(ss_h, red3);

    const float inv_fh = 1.f / (float)FH;
    float mu_i  = sum_i * inv_fh;
    float var_i = sumq_i * inv_fh - mu_i * mu_i;
    float rs_i  = rsqrtf(var_i + 1e-5f);
    float mu_h  = sum_h * inv_fh;
    float var_h = sumq_h * inv_fh - mu_h * mu_h;
    float rs_h  = rsqrtf(var_h + 1e-5f);

    #pragma unroll
    for (int p = 0; p < 16; p++) {
        int j = tid + p * 256;
        float gi = (vi[p] - mu_i) * rs_i * ln_i_w[j] + ln_i_b[j];
        float gh = (vh[p] - mu_h) * rs_h * ln_h_w[j] + ln_h_b[j];
        gates[j] = gi + gh;
    }
    __syncthreads();

    float cvals[4];
    float s_c = 0.f, ss_c = 0.f;
    #pragma unroll
    for (int p = 0; p < 4; p++) {
        int h  = tid + p * 256;
        float in_g = sigmoidf_(gates[h]);
        float f_g  = sigmoidf_(gates[HDIM + h]);
        float g_g  = tanhf(gates[2 * HDIM + h]);
        float c = f_g * cx[(size_t)b * HDIM + h] + in_g * g_g;
        cvals[p] = c;
        s_c += c; ss_c += c * c;
    }
    float sum_c  = block_sum(s_c,  red4);
    float sumq_c = block_sum(ss_c, red5);
    const float inv_h = 1.f / (float)HDIM;
    float mu_c  = sum_c * inv_h;
    float var_c = sumq_c * inv_h - mu_c * mu_c;
    float rs_c  = rsqrtf(var_c + 1e-5f);

    #pragma unroll
    for (int p = 0; p < 4; p++) {
        int h = tid + p * 256;
        float cy = (cvals[p] - mu_c) * rs_c * ln_c_w[h] + ln_c_b[h];
        float o_g = sigmoidf_(gates[3 * HDIM + h]);
        float hy = o_g * tanhf(cy);
        out[(size_t)b * HDIM + h] = hy;
        out[(size_t)BATCH * HDIM + (size_t)b * HDIM + h] = cy;
    }
}

// ---------------------------------------------------------------------------
extern "C" void kernel_launch(void* const* d_in, const int* in_sizes, int n_in,
                              void* d_out, int out_size)
{
    const float* input  = (const float*)d_in[0];
    const float* hx     = (const float*)d_in[1];
    const float* cx     = (const float*)d_in[2];
    const float* wih    = (const float*)d_in[3];
    const float* whh    = (const float*)d_in[4];
    const float* ln_i_w = (const float*)d_in[5];
    const float* ln_i_b = (const float*)d_in[6];
    const float* ln_h_w = (const float*)d_in[7];
    const float* ln_h_b = (const float*)d_in[8];
    const float* ln_c_w = (const float*)d_in[9];
    const float* ln_c_b = (const float*)d_in[10];
    float* out = (float*)d_out;

    cudaFuncSetAttribute(gemm_tc_kernel,
                         cudaFuncAttributeMaxDynamicSharedMemorySize, SMEM_TOTAL);

    float *dA, *dH, *dWi, *dWh;
    cudaGetSymbolAddress((void**)&dA,  g_A);
    cudaGetSymbolAddress((void**)&dH,  g_H);
    cudaGetSymbolAddress((void**)&dWi, g_Wi);
    cudaGetSymbolAddress((void**)&dWh, g_Wh);

    // pre-round operands to tf32 (RNA) once
    round_tf32_kernel<<<512, 256>>>(input, dA, (BATCH * KDIM) / 4);
    round_tf32_kernel<<<512, 256>>>(hx,    dH, (BATCH * KDIM) / 4);
    round_tf32_kernel<<<512, 256>>>(wih,   dWi, (FH * KDIM) / 4);
    round_tf32_kernel<<<512, 256>>>(whh,   dWh, (FH * KDIM) / 4);

    dim3 grid(FH / BN, BATCH / BM, 2);
    gemm_tc_kernel<<<grid, 256, SMEM_TOTAL>>>(dA, dH, dWi, dWh);
    fuse_kernel<<<BATCH, 256>>>(cx, ln_i_w, ln_i_b, ln_h_w, ln_h_b, ln_c_w, ln_c_b, out);
}

// round 5
// speedup vs baseline: 1.5715x; 1.1019x over previous
#include <cuda_runtime.h>
#include <math.h>
#include <stdint.h>

#define BATCH 8192
#define KDIM  1024
#define HDIM  1024
#define FH    4096

// Scratch: raw gate pre-activations + tf32-prerounded operand copies.
__device__ float g_ig[(size_t)BATCH * FH];
__device__ float g_hg[(size_t)BATCH * FH];
__device__ float g_A [(size_t)BATCH * KDIM];
__device__ float g_H [(size_t)BATCH * KDIM];
__device__ float g_Wi[(size_t)FH * KDIM];
__device__ float g_Wh[(size_t)FH * KDIM];

// ---------------------------------------------------------------------------
// tf32 pre-rounding (RNA), all 4 tensors in one launch (blockIdx.y selects).
// ---------------------------------------------------------------------------
__device__ __forceinline__ float to_tf32(float x) {
    uint32_t u;
    asm("cvt.rna.tf32.f32 %0, %1;" : "=r"(u) : "f"(x));
    return __uint_as_float(u);
}

__global__ void __launch_bounds__(256)
round_all_kernel(const float* __restrict__ s0, const float* __restrict__ s1,
                 const float* __restrict__ s2, const float* __restrict__ s3,
                 float* __restrict__ d0, float* __restrict__ d1,
                 float* __restrict__ d2, float* __restrict__ d3)
{
    const float* src; float* dst; int n4;
    switch (blockIdx.y) {
        case 0: src = s0; dst = d0; n4 = (BATCH * KDIM) / 4; break;
        case 1: src = s1; dst = d1; n4 = (BATCH * KDIM) / 4; break;
        case 2: src = s2; dst = d2; n4 = (FH * KDIM) / 4; break;
        default: src = s3; dst = d3; n4 = (FH * KDIM) / 4; break;
    }
    int i = blockIdx.x * blockDim.x + threadIdx.x;
    int stride = gridDim.x * blockDim.x;
    for (; i < n4; i += stride) {
        float4 v = ((const float4*)src)[i];
        v.x = to_tf32(v.x); v.y = to_tf32(v.y);
        v.z = to_tf32(v.z); v.w = to_tf32(v.w);
        ((float4*)dst)[i] = v;
    }
}

// ---------------------------------------------------------------------------
// GEMM: out[m,n] = sum_k A[m,k] * W[n,k]  (mma.sync tf32 + ldmatrix + cp.async)
// CTA tile 128x256x64, 2 stages, 8 warps (2x4), warp tile 64x64.
// ---------------------------------------------------------------------------
#define BM 128
#define BN 256
#define BK 64
#define NCHUNK (KDIM / BK)                 // 16
#define ROWW  (BK + 4)                     // 68 floats per smem row
#define A_BYTES (BM * ROWW * 4)            // 34816
#define B_BYTES (BN * ROWW * 4)            // 69632
#define STAGE_BYTES (A_BYTES + B_BYTES)    // 104448
#define SMEM_TOTAL (2 * STAGE_BYTES)       // 208896

__device__ __forceinline__ uint32_t smem_u32(const void* p) {
    uint32_t a;
    asm("{ .reg .u64 t; cvta.to.shared.u64 t, %1; cvt.u32.u64 %0, t; }" : "=r"(a) : "l"(p));
    return a;
}

__device__ __forceinline__ void cp16(uint32_t saddr, const void* g) {
    asm volatile("cp.async.cg.shared.global [%0], [%1], 16;" :: "r"(saddr), "l"(g));
}
#define CP_COMMIT() asm volatile("cp.async.commit_group;" ::: "memory")
#define CP_WAIT_1() asm volatile("cp.async.wait_group 1;" ::: "memory")

__device__ __forceinline__ void ldsm4(uint32_t& r0, uint32_t& r1, uint32_t& r2, uint32_t& r3,
                                      uint32_t addr) {
    asm volatile("ldmatrix.sync.aligned.m8n8.x4.shared.b16 {%0,%1,%2,%3}, [%4];"
                 : "=r"(r0), "=r"(r1), "=r"(r2), "=r"(r3) : "r"(addr));
}

__device__ __forceinline__ void mma_tf32(float c[4], const uint32_t a[4], const uint32_t b[2]) {
    asm volatile(
        "mma.sync.aligned.m16n8k8.row.col.f32.tf32.tf32.f32 "
        "{%0,%1,%2,%3}, {%4,%5,%6,%7}, {%8,%9}, {%0,%1,%2,%3};"
        : "+f"(c[0]), "+f"(c[1]), "+f"(c[2]), "+f"(c[3])
        : "r"(a[0]), "r"(a[1]), "r"(a[2]), "r"(a[3]),
          "r"(b[0]), "r"(b[1]));
}

__global__ void __launch_bounds__(256, 1)
gemm_tc_kernel(const float* __restrict__ gA, const float* __restrict__ gH,
               const float* __restrict__ gWi, const float* __restrict__ gWh)
{
    extern __shared__ char smem[];
    const uint32_t sbase = smem_u32(smem);

    const float* A   = (blockIdx.z == 0) ? gA  : gH;
    const float* W   = (blockIdx.z == 0) ? gWi : gWh;
    float*       out = (blockIdx.z == 0) ? g_ig : g_hg;

    const int tid  = threadIdx.x;
    const int wid  = tid >> 5;
    const int lane = tid & 31;
    const int wm   = wid >> 2;     // 0..1 -> 64-row slab
    const int wn   = wid & 3;      // 0..3 -> 64-col slab
    const int m0   = blockIdx.y * BM;
    const int n0   = blockIdx.x * BN;

    // cp.async loader mapping: 16 float4 chunks per row
    const int ldrow = tid >> 4;    // base row
    const int ldc4  = tid & 15;    // 16B chunk in row

    auto load_stage = [&](int st, int c) {
        const uint32_t sA = sbase + st * STAGE_BYTES;
        const uint32_t sB = sA + A_BYTES;
        const int kt = c * BK;
        #pragma unroll
        for (int i = 0; i < 8; i++) {
            int row = ldrow + i * 16;
            cp16(sA + (row * ROWW + ldc4 * 4) * 4,
                 &A[(size_t)(m0 + row) * KDIM + kt + ldc4 * 4]);
        }
        #pragma unroll
        for (int i = 0; i < 16; i++) {
            int row = ldrow + i * 16;
            cp16(sB + (row * ROWW + ldc4 * 4) * 4,
                 &W[(size_t)(n0 + row) * KDIM + kt + ldc4 * 4]);
        }
    };

    // ldmatrix per-lane base offsets (bytes within a stage)
    const int lt  = lane >> 3;      // tile index 0..3
    const int lri = lane & 7;       // row within tile
    uint32_t offA[4];
    {
        int row = wm * 64 + lri + (lt & 1) * 8;
        int col = (lt >> 1) * 4;
        #pragma unroll
        for (int mt = 0; mt < 4; mt++)
            offA[mt] = ((row + mt * 16) * ROWW + col) * 4;
    }
    uint32_t offB[4];
    {
        int row = wn * 64 + lri + (lt >> 1) * 8;
        int col = (lt & 1) * 4;
        #pragma unroll
        for (int nt2 = 0; nt2 < 4; nt2++)
            offB[nt2] = (uint32_t)A_BYTES + ((row + nt2 * 16) * ROWW + col) * 4;
    }

    float acc[4][8][4];
    #pragma unroll
    for (int mt = 0; mt < 4; mt++)
        #pragma unroll
        for (int nt = 0; nt < 8; nt++)
            #pragma unroll
            for (int r = 0; r < 4; r++)
                acc[mt][nt][r] = 0.f;

    load_stage(0, 0); CP_COMMIT();
    load_stage(1, 1); CP_COMMIT();

    for (int c = 0; c < NCHUNK; c++) {
        CP_WAIT_1();
        __syncthreads();

        const uint32_t sb = sbase + (c & 1) * STAGE_BYTES;

        #pragma unroll
        for (int kk = 0; kk < BK; kk += 8) {
            const uint32_t kb = kk * 4;
            uint32_t af[4][4];
            #pragma unroll
            for (int mt = 0; mt < 4; mt++)
                ldsm4(af[mt][0], af[mt][1], af[mt][2], af[mt][3], sb + offA[mt] + kb);
            uint32_t bf[8][2];
            #pragma unroll
            for (int nt2 = 0; nt2 < 4; nt2++)
                ldsm4(bf[2*nt2][0], bf[2*nt2][1], bf[2*nt2+1][0], bf[2*nt2+1][1],
                      sb + offB[nt2] + kb);
            #pragma unroll
            for (int mt = 0; mt < 4; mt++)
                #pragma unroll
                for (int nt = 0; nt < 8; nt++)
                    mma_tf32(acc[mt][nt], af[mt], bf[nt]);
        }

        __syncthreads();
        if (c + 2 < NCHUNK) load_stage(c & 1, c + 2);
        CP_COMMIT();
    }

    // epilogue
    #pragma unroll
    for (int mt = 0; mt < 4; mt++) {
        int row0 = m0 + wm * 64 + mt * 16 + (lane >> 2);
        #pragma unroll
        for (int nt = 0; nt < 8; nt++) {
            int col0 = n0 + wn * 64 + nt * 8 + 2 * (lane & 3);
            *(float2*)&out[(size_t)row0 * FH + col0] =
                make_float2(acc[mt][nt][0], acc[mt][nt][1]);
            *(float2*)&out[(size_t)(row0 + 8) * FH + col0] =
                make_float2(acc[mt][nt][2], acc[mt][nt][3]);
        }
    }
}

// ---------------------------------------------------------------------------
// Fused LayerNorm + LSTM gates + cell LayerNorm. float4 path.
// RACE FIX vs R4: each block reduction uses its own shared buffer.
// ---------------------------------------------------------------------------
__device__ __forceinline__ float sigmoidf_(float x) {
    return 1.f / (1.f + expf(-x));
}

// paired (sum, sumsq) block reduction over 256 threads; sh unique per call
__device__ __forceinline__ float2 block_sum2(float2 v, float2* sh) {
    #pragma unroll
    for (int o = 16; o > 0; o >>= 1) {
        v.x += __shfl_down_sync(0xffffffffu, v.x, o);
        v.y += __shfl_down_sync(0xffffffffu, v.y, o);
    }
    int lane = threadIdx.x & 31, w = threadIdx.x >> 5;
    if (lane == 0) sh[w] = v;
    __syncthreads();
    if (w == 0) {
        float2 t = (lane < 8) ? sh[lane] : make_float2(0.f, 0.f);
        #pragma unroll
        for (int o = 4; o > 0; o >>= 1) {
            t.x += __shfl_down_sync(0xffffffffu, t.x, o);
            t.y += __shfl_down_sync(0xffffffffu, t.y, o);
        }
        if (lane == 0) sh[0] = t;
    }
    __syncthreads();
    return sh[0];
}

__global__ void __launch_bounds__(256)
fuse_kernel(const float* __restrict__ cx,
            const float* __restrict__ ln_i_w, const float* __restrict__ ln_i_b,
            const float* __restrict__ ln_h_w, const float* __restrict__ ln_h_b,
            const float* __restrict__ ln_c_w, const float* __restrict__ ln_c_b,
            float* __restrict__ out)
{
    const int b   = blockIdx.x;
    const int tid = threadIdx.x;
    const float4* ig4 = (const float4*)(g_ig + (size_t)b * FH);
    const float4* hg4 = (const float4*)(g_hg + (size_t)b * FH);

    __shared__ float4 gates4[FH / 4];
    __shared__ float2 red_i[8], red_h[8], red_c[8];

    float4 vi[4], vh[4];
    float2 si = make_float2(0.f, 0.f), sh_ = make_float2(0.f, 0.f);
    #pragma unroll
    for (int p = 0; p < 4; p++) {
        int j = tid + p * 256;
        float4 a = ig4[j], c = hg4[j];
        vi[p] = a; vh[p] = c;
        si.x += a.x + a.y + a.z + a.w;
        si.y += a.x*a.x + a.y*a.y + a.z*a.z + a.w*a.w;
        sh_.x += c.x + c.y + c.z + c.w;
        sh_.y += c.x*c.x + c.y*c.y + c.z*c.z + c.w*c.w;
    }
    float2 ri = block_sum2(si, red_i);
    float2 rh = block_sum2(sh_, red_h);

    const float inv_fh = 1.f / (float)FH;
    float mu_i = ri.x * inv_fh;
    float rs_i = rsqrtf(ri.y * inv_fh - mu_i * mu_i + 1e-5f);
    float mu_h = rh.x * inv_fh;
    float rs_h = rsqrtf(rh.y * inv_fh - mu_h * mu_h + 1e-5f);

    #pragma unroll
    for (int p = 0; p < 4; p++) {
        int j = tid + p * 256;
        float4 wi = ((const float4*)ln_i_w)[j], bi = ((const float4*)ln_i_b)[j];
        float4 wh = ((const float4*)ln_h_w)[j], bh = ((const float4*)ln_h_b)[j];
        float4 a = vi[p], c = vh[p], g;
        g.x = (a.x - mu_i) * rs_i * wi.x + bi.x + (c.x - mu_h) * rs_h * wh.x + bh.x;
        g.y = (a.y - mu_i) * rs_i * wi.y + bi.y + (c.y - mu_h) * rs_h * wh.y + bh.y;
        g.z = (a.z - mu_i) * rs_i * wi.z + bi.z + (c.z - mu_h) * rs_h * wh.z + bh.z;
        g.w = (a.w - mu_i) * rs_i * wi.w + bi.w + (c.w - mu_h) * rs_h * wh.w + bh.w;
        gates4[j] = g;
    }
    __syncthreads();

    float4 gi = gates4[tid];
    float4 gf = gates4[256 + tid];
    float4 gg = gates4[512 + tid];
    float4 go = gates4[768 + tid];
    float4 c4 = ((const float4*)cx)[b * 256 + tid];

    float4 cv;
    cv.x = sigmoidf_(gf.x) * c4.x + sigmoidf_(gi.x) * tanhf(gg.x);
    cv.y = sigmoidf_(gf.y) * c4.y + sigmoidf_(gi.y) * tanhf(gg.y);
    cv.z = sigmoidf_(gf.z) * c4.z + sigmoidf_(gi.z) * tanhf(gg.z);
    cv.w = sigmoidf_(gf.w) * c4.w + sigmoidf_(gi.w) * tanhf(gg.w);

    float2 sc = make_float2(cv.x + cv.y + cv.z + cv.w,
                            cv.x*cv.x + cv.y*cv.y + cv.z*cv.z + cv.w*cv.w);
    float2 rc = block_sum2(sc, red_c);
    const float inv_h = 1.f / (float)HDIM;
    float mu_c = rc.x * inv_h;
    float rs_c = rsqrtf(rc.y * inv_h - mu_c * mu_c + 1e-5f);

    float4 wc = ((const float4*)ln_c_w)[tid], bc = ((const float4*)ln_c_b)[tid];
    float4 cy, hy;
    cy.x = (cv.x - mu_c) * rs_c * wc.x + bc.x;  hy.x = sigmoidf_(go.x) * tanhf(cy.x);
    cy.y = (cv.y - mu_c) * rs_c * wc.y + bc.y;  hy.y = sigmoidf_(go.y) * tanhf(cy.y);
    cy.z = (cv.z - mu_c) * rs_c * wc.z + bc.z;  hy.z = sigmoidf_(go.z) * tanhf(cy.z);
    cy.w = (cv.w - mu_c) * rs_c * wc.w + bc.w;  hy.w = sigmoidf_(go.w) * tanhf(cy.w);

    ((float4*)out)[(size_t)b * 256 + tid] = hy;
    ((float4*)out)[(size_t)BATCH * 256 + (size_t)b * 256 + tid] = cy;
}

// ---------------------------------------------------------------------------
extern "C" void kernel_launch(void* const* d_in, const int* in_sizes, int n_in,
                              void* d_out, int out_size)
{
    const float* input  = (const float*)d_in[0];
    const float* hx     = (const float*)d_in[1];
    const float* cx     = (const float*)d_in[2];
    const float* wih    = (const float*)d_in[3];
    const float* whh    = (const float*)d_in[4];
    const float* ln_i_w = (const float*)d_in[5];
    const float* ln_i_b = (const float*)d_in[6];
    const float* ln_h_w = (const float*)d_in[7];
    const float* ln_h_b = (const float*)d_in[8];
    const float* ln_c_w = (const float*)d_in[9];
    const float* ln_c_b = (const float*)d_in[10];
    float* out = (float*)d_out;

    cudaFuncSetAttribute(gemm_tc_kernel,
                         cudaFuncAttributeMaxDynamicSharedMemorySize, SMEM_TOTAL);

    float *dA, *dH, *dWi, *dWh;
    cudaGetSymbolAddress((void**)&dA,  g_A);
    cudaGetSymbolAddress((void**)&dH,  g_H);
    cudaGetSymbolAddress((void**)&dWi, g_Wi);
    cudaGetSymbolAddress((void**)&dWh, g_Wh);

    round_all_kernel<<<dim3(160, 4), 256>>>(input, hx, wih, whh, dA, dH, dWi, dWh);

    dim3 grid(FH / BN, BATCH / BM, 2);
    gemm_tc_kernel<<<grid, 256, SMEM_TOTAL>>>(dA, dH, dWi, dWh);
    fuse_kernel<<<BATCH, 256>>>(cx, ln_i_w, ln_i_b, ln_h_w, ln_h_b, ln_c_w, ln_c_b, out);
}